// round 3
// baseline (speedup 1.0000x reference)
#include <cuda_runtime.h>
#include <math.h>

#define Bc 4
#define Sc 1024
#define DIMc 1024
#define Hc 16
#define DHc 64
#define Mc (Bc * Sc)

// Scratch (allocation-free rule: __device__ globals)
__device__ float g_q[Mc * DIMc];
__device__ float g_k[Mc * DIMc];
__device__ float g_v[Mc * DIMc];
__device__ float g_o[Mc * DIMc];
__device__ float g_cs[Sc * 32];
__device__ float g_sn[Sc * 32];

// ----------------------------------------------------------------------------
// SGEMM: C[m][n] = sum_k A[m][k] * W[n][k] + bias[n]
// 128x128x16 tiles, 256 threads, 8x8 microtile, double-buffered smem.
// ----------------------------------------------------------------------------
__device__ __forceinline__ void sgemm_body(
    const float* __restrict__ A, const float* __restrict__ W,
    const float* __restrict__ bias, float* __restrict__ C, int K, int N) {
  __shared__ float As[2][16][132];
  __shared__ float Bs[2][16][132];
  const int tid = threadIdx.x;
  const int tx = tid & 15, ty = tid >> 4;
  const int row0 = blockIdx.y * 128, col0 = blockIdx.x * 128;
  const float* Ab = A + (size_t)row0 * K;
  const float* Wb = W + (size_t)col0 * K;
  const int lr = tid >> 1;        // 0..127
  const int lc = (tid & 1) * 8;   // 0 or 8

  float acc[8][8];
#pragma unroll
  for (int i = 0; i < 8; i++)
#pragma unroll
    for (int j = 0; j < 8; j++) acc[i][j] = 0.f;

  float4 pa0, pa1, pb0, pb1;
  // Load tile 0
  pa0 = *(const float4*)(Ab + (size_t)lr * K + lc);
  pa1 = *(const float4*)(Ab + (size_t)lr * K + lc + 4);
  pb0 = *(const float4*)(Wb + (size_t)lr * K + lc);
  pb1 = *(const float4*)(Wb + (size_t)lr * K + lc + 4);
  As[0][lc + 0][lr] = pa0.x; As[0][lc + 1][lr] = pa0.y;
  As[0][lc + 2][lr] = pa0.z; As[0][lc + 3][lr] = pa0.w;
  As[0][lc + 4][lr] = pa1.x; As[0][lc + 5][lr] = pa1.y;
  As[0][lc + 6][lr] = pa1.z; As[0][lc + 7][lr] = pa1.w;
  Bs[0][lc + 0][lr] = pb0.x; Bs[0][lc + 1][lr] = pb0.y;
  Bs[0][lc + 2][lr] = pb0.z; Bs[0][lc + 3][lr] = pb0.w;
  Bs[0][lc + 4][lr] = pb1.x; Bs[0][lc + 5][lr] = pb1.y;
  Bs[0][lc + 6][lr] = pb1.z; Bs[0][lc + 7][lr] = pb1.w;
  __syncthreads();

  const int T = K >> 4;
  for (int t = 0; t < T; t++) {
    const int cur = t & 1;
    if (t + 1 < T) {
      int k0 = (t + 1) << 4;
      pa0 = *(const float4*)(Ab + (size_t)lr * K + k0 + lc);
      pa1 = *(const float4*)(Ab + (size_t)lr * K + k0 + lc + 4);
      pb0 = *(const float4*)(Wb + (size_t)lr * K + k0 + lc);
      pb1 = *(const float4*)(Wb + (size_t)lr * K + k0 + lc + 4);
    }
#pragma unroll
    for (int k = 0; k < 16; k++) {
      float4 a0 = *(const float4*)&As[cur][k][ty * 4];
      float4 a1 = *(const float4*)&As[cur][k][64 + ty * 4];
      float4 b0 = *(const float4*)&Bs[cur][k][tx * 4];
      float4 b1 = *(const float4*)&Bs[cur][k][64 + tx * 4];
      float ar[8] = {a0.x, a0.y, a0.z, a0.w, a1.x, a1.y, a1.z, a1.w};
      float br[8] = {b0.x, b0.y, b0.z, b0.w, b1.x, b1.y, b1.z, b1.w};
#pragma unroll
      for (int i = 0; i < 8; i++)
#pragma unroll
        for (int j = 0; j < 8; j++) acc[i][j] = fmaf(ar[i], br[j], acc[i][j]);
    }
    if (t + 1 < T) {
      const int nxt = cur ^ 1;
      As[nxt][lc + 0][lr] = pa0.x; As[nxt][lc + 1][lr] = pa0.y;
      As[nxt][lc + 2][lr] = pa0.z; As[nxt][lc + 3][lr] = pa0.w;
      As[nxt][lc + 4][lr] = pa1.x; As[nxt][lc + 5][lr] = pa1.y;
      As[nxt][lc + 6][lr] = pa1.z; As[nxt][lc + 7][lr] = pa1.w;
      Bs[nxt][lc + 0][lr] = pb0.x; Bs[nxt][lc + 1][lr] = pb0.y;
      Bs[nxt][lc + 2][lr] = pb0.z; Bs[nxt][lc + 3][lr] = pb0.w;
      Bs[nxt][lc + 4][lr] = pb1.x; Bs[nxt][lc + 5][lr] = pb1.y;
      Bs[nxt][lc + 6][lr] = pb1.z; Bs[nxt][lc + 7][lr] = pb1.w;
    }
    __syncthreads();
  }

#pragma unroll
  for (int i = 0; i < 8; i++) {
    int r = row0 + ((i < 4) ? (ty * 4 + i) : (64 + ty * 4 + (i - 4)));
#pragma unroll
    for (int jh = 0; jh < 2; jh++) {
      int c = col0 + jh * 64 + tx * 4;
      float4 o;
      o.x = acc[i][jh * 4 + 0] + bias[c + 0];
      o.y = acc[i][jh * 4 + 1] + bias[c + 1];
      o.z = acc[i][jh * 4 + 2] + bias[c + 2];
      o.w = acc[i][jh * 4 + 3] + bias[c + 3];
      *(float4*)(C + (size_t)r * N + c) = o;
    }
  }
}

__global__ void __launch_bounds__(256) sgemm_bias(
    const float* __restrict__ A, const float* __restrict__ W,
    const float* __restrict__ bias, float* __restrict__ C, int K, int N) {
  sgemm_body(A, W, bias, C, K, N);
}

__global__ void __launch_bounds__(256) sgemm_bias_qkv(
    const float* __restrict__ A,
    const float* __restrict__ Wq, const float* __restrict__ bq, float* __restrict__ Cq,
    const float* __restrict__ Wk, const float* __restrict__ bk, float* __restrict__ Ck,
    const float* __restrict__ Wv, const float* __restrict__ bv, float* __restrict__ Cv,
    int K, int N) {
  const float* W; const float* bias; float* C;
  if (blockIdx.z == 0)      { W = Wq; bias = bq; C = Cq; }
  else if (blockIdx.z == 1) { W = Wk; bias = bk; C = Ck; }
  else                      { W = Wv; bias = bv; C = Cv; }
  sgemm_body(A, W, bias, C, K, N);
}

// ----------------------------------------------------------------------------
// RoPE: cos/sin table (double, exact) + memory-bound fp32 apply.
// ----------------------------------------------------------------------------
__global__ void rope_table_kernel() {
  int idx = blockIdx.x * blockDim.x + threadIdx.x;
  if (idx >= Sc * 32) return;
  int j = idx & 31;
  int s = idx >> 5;
  double freq = exp(-(double)j * (log(10000.0) / 32.0));
  double ang = (double)s * freq;
  g_cs[idx] = (float)cos(ang);
  g_sn[idx] = (float)sin(ang);
}

__global__ void __launch_bounds__(256) rope_apply_kernel(float* __restrict__ q,
                                                         float* __restrict__ k) {
  int idx = blockIdx.x * blockDim.x + threadIdx.x;
  if (idx >= Mc * Hc * 32) return;
  int j = idx & 31;
  int h = (idx >> 5) & (Hc - 1);
  int m = idx >> 9;
  int s = m & (Sc - 1);
  float cs = g_cs[s * 32 + j];
  float sn = g_sn[s * 32 + j];
  size_t base = (size_t)m * DIMc + h * DHc;
  float q1 = q[base + j], q2 = q[base + j + 32];
  q[base + j]      = fmaf(q1, cs, -q2 * sn);
  q[base + j + 32] = fmaf(q2, cs,  q1 * sn);
  float k1 = k[base + j], k2 = k[base + j + 32];
  k[base + j]      = fmaf(k1, cs, -k2 * sn);
  k[base + j + 32] = fmaf(k2, cs,  k1 * sn);
}

// ----------------------------------------------------------------------------
// Flash attention fp32 v2: 128 q-rows/block, 64-col kv tiles, 128 threads,
// 8x8 microtile (1 B smem / FMA). Online softmax, tx-staggered P store.
// ----------------------------------------------------------------------------
#define PQ 132
#define PK 68
#define FLASH_SMEM ((64 * PQ + 64 * PK + 64 * PK + 64 * PQ) * 4)

__global__ void __launch_bounds__(128) flash_kernel(
    const float* __restrict__ q, const float* __restrict__ k,
    const float* __restrict__ v, float* __restrict__ o) {
  extern __shared__ float sm[];
  float* Qs = sm;                   // [d][i] 64 x PQ (i over 128 q rows)
  float* Ks = Qs + 64 * PQ;         // [d][j] 64 x PK
  float* Vs = Ks + 64 * PK;         // [j][d] 64 x PK
  float* Ps = Vs + 64 * PK;         // [j][i] 64 x PQ

  const int tid = threadIdx.x;
  const int tx = tid & 7;           // 0..7  (kv cols / d cols, x8)
  const int ty = tid >> 3;          // 0..15 (q rows, x8)
  const int b = blockIdx.y >> 4, h = blockIdx.y & 15;
  const int q0 = blockIdx.x * 128;
  const float* qb = q + (size_t)b * Sc * DIMc + h * DHc;
  const float* kb = k + (size_t)b * Sc * DIMc + h * DHc;
  const float* vb = v + (size_t)b * Sc * DIMc + h * DHc;

  // Load Q tile (128 x 64), transposed into Qs[d][i]
#pragma unroll
  for (int it = 0; it < 16; it++) {
    int idx = tid + it * 128;
    int i = idx >> 4, d4 = (idx & 15) * 4;
    float4 t4 = *(const float4*)(qb + (size_t)(q0 + i) * DIMc + d4);
    Qs[(d4 + 0) * PQ + i] = t4.x;
    Qs[(d4 + 1) * PQ + i] = t4.y;
    Qs[(d4 + 2) * PQ + i] = t4.z;
    Qs[(d4 + 3) * PQ + i] = t4.w;
  }

  float m_i[8], l_i[8], acc[8][8];
#pragma unroll
  for (int r = 0; r < 8; r++) {
    m_i[r] = -INFINITY;
    l_i[r] = 0.f;
#pragma unroll
    for (int c = 0; c < 8; c++) acc[r][c] = 0.f;
  }

  const float scale = 0.125f;  // 1/sqrt(64)

  for (int t = 0; t < 16; t++) {
    int kv0 = t * 64;
    __syncthreads();  // prev-iteration readers of Ks/Vs done
    // Load K (transposed) and V tiles: 64 rows x 64 d
#pragma unroll
    for (int it = 0; it < 8; it++) {
      int idx = tid + it * 128;
      int j = idx >> 4, d4 = (idx & 15) * 4;
      float4 kk = *(const float4*)(kb + (size_t)(kv0 + j) * DIMc + d4);
      Ks[(d4 + 0) * PK + j] = kk.x;
      Ks[(d4 + 1) * PK + j] = kk.y;
      Ks[(d4 + 2) * PK + j] = kk.z;
      Ks[(d4 + 3) * PK + j] = kk.w;
      float4 vv = *(const float4*)(vb + (size_t)(kv0 + j) * DIMc + d4);
      *(float4*)(Vs + j * PK + d4) = vv;
    }
    __syncthreads();

    // S = Q K^T : 128x64, 8x8 per thread
    float s[8][8];
#pragma unroll
    for (int r = 0; r < 8; r++)
#pragma unroll
      for (int c = 0; c < 8; c++) s[r][c] = 0.f;
#pragma unroll 8
    for (int d = 0; d < 64; d++) {
      float4 a0 = *(const float4*)&Qs[d * PQ + ty * 8];
      float4 a1 = *(const float4*)&Qs[d * PQ + ty * 8 + 4];
      float4 b0 = *(const float4*)&Ks[d * PK + tx * 8];
      float4 b1 = *(const float4*)&Ks[d * PK + tx * 8 + 4];
      float ar[8] = {a0.x, a0.y, a0.z, a0.w, a1.x, a1.y, a1.z, a1.w};
      float br[8] = {b0.x, b0.y, b0.z, b0.w, b1.x, b1.y, b1.z, b1.w};
#pragma unroll
      for (int r = 0; r < 8; r++)
#pragma unroll
        for (int c = 0; c < 8; c++) s[r][c] = fmaf(ar[r], br[c], s[r][c]);
    }

    // Online softmax per row; 8 lanes (tx) per row group share ty
#pragma unroll
    for (int r = 0; r < 8; r++) {
#pragma unroll
      for (int c = 0; c < 8; c++) s[r][c] *= scale;
      float mx = s[r][0];
#pragma unroll
      for (int c = 1; c < 8; c++) mx = fmaxf(mx, s[r][c]);
#pragma unroll
      for (int off = 4; off > 0; off >>= 1)
        mx = fmaxf(mx, __shfl_xor_sync(0xffffffffu, mx, off));
      float mn = fmaxf(m_i[r], mx);
      float corr = __expf(m_i[r] - mn);
      float rs = 0.f;
      // staggered column order -> conflict-reduced scalar stores
#pragma unroll
      for (int cc = 0; cc < 8; cc++) {
        int c = (cc + tx) & 7;
        float p = __expf(s[r][c] - mn);
        rs += p;
        Ps[(tx * 8 + c) * PQ + ty * 8 + r] = p;
      }
#pragma unroll
      for (int off = 4; off > 0; off >>= 1)
        rs += __shfl_xor_sync(0xffffffffu, rs, off);
      l_i[r] = l_i[r] * corr + rs;
      m_i[r] = mn;
#pragma unroll
      for (int c = 0; c < 8; c++) acc[r][c] *= corr;
    }
    __syncthreads();

    // O += P V : 128x64, 8x8 per thread
#pragma unroll 8
    for (int j = 0; j < 64; j++) {
      float4 a0 = *(const float4*)&Ps[j * PQ + ty * 8];
      float4 a1 = *(const float4*)&Ps[j * PQ + ty * 8 + 4];
      float4 b0 = *(const float4*)&Vs[j * PK + tx * 8];
      float4 b1 = *(const float4*)&Vs[j * PK + tx * 8 + 4];
      float ar[8] = {a0.x, a0.y, a0.z, a0.w, a1.x, a1.y, a1.z, a1.w};
      float br[8] = {b0.x, b0.y, b0.z, b0.w, b1.x, b1.y, b1.z, b1.w};
#pragma unroll
      for (int r = 0; r < 8; r++)
#pragma unroll
        for (int c = 0; c < 8; c++) acc[r][c] = fmaf(ar[r], br[c], acc[r][c]);
    }
  }

  // Writeback o[b, q0 + ty*8 + r, h, tx*8 + c]
#pragma unroll
  for (int r = 0; r < 8; r++) {
    float inv = 1.f / l_i[r];
    float4 o0 = make_float4(acc[r][0] * inv, acc[r][1] * inv,
                            acc[r][2] * inv, acc[r][3] * inv);
    float4 o1 = make_float4(acc[r][4] * inv, acc[r][5] * inv,
                            acc[r][6] * inv, acc[r][7] * inv);
    float* dst = o + (size_t)(b * Sc + q0 + ty * 8 + r) * DIMc + h * DHc + tx * 8;
    *(float4*)dst = o0;
    *(float4*)(dst + 4) = o1;
  }
}

// ----------------------------------------------------------------------------
extern "C" void kernel_launch(void* const* d_in, const int* in_sizes, int n_in,
                              void* d_out, int out_size) {
  const float* x  = (const float*)d_in[0];
  const float* Wq = (const float*)d_in[1];
  const float* bq = (const float*)d_in[2];
  const float* Wk = (const float*)d_in[3];
  const float* bk = (const float*)d_in[4];
  const float* Wv = (const float*)d_in[5];
  const float* bv = (const float*)d_in[6];
  const float* Wo = (const float*)d_in[7];
  const float* bo = (const float*)d_in[8];
  float* out = (float*)d_out;

  float *qp, *kp, *vp, *op;
  cudaGetSymbolAddress((void**)&qp, g_q);
  cudaGetSymbolAddress((void**)&kp, g_k);
  cudaGetSymbolAddress((void**)&vp, g_v);
  cudaGetSymbolAddress((void**)&op, g_o);

  rope_table_kernel<<<(Sc * 32 + 255) / 256, 256>>>();

  dim3 gqkv(DIMc / 128, Mc / 128, 3);
  sgemm_bias_qkv<<<gqkv, 256>>>(x, Wq, bq, qp, Wk, bk, kp, Wv, bv, vp, DIMc, DIMc);

  int total = Mc * Hc * 32;
  rope_apply_kernel<<<(total + 255) / 256, 256>>>(qp, kp);

  cudaFuncSetAttribute(flash_kernel, cudaFuncAttributeMaxDynamicSharedMemorySize,
                       FLASH_SMEM);
  flash_kernel<<<dim3(Sc / 128, Bc * Hc), 128, FLASH_SMEM>>>(qp, kp, vp, op);

  dim3 gg(DIMc / 128, Mc / 128);
  sgemm_bias<<<gg, 256>>>(op, Wo, bo, out, DIMc, DIMc);
}

// round 6
// speedup vs baseline: 1.7230x; 1.7230x over previous
#include <cuda_runtime.h>
#include <cuda_bf16.h>
#include <math.h>
#include <stdint.h>

#define Bc 4
#define Sc 1024
#define DIMc 1024
#define Hc 16
#define DHc 64
#define Mc (Bc * Sc)

// ---------------- scratch (__device__ globals; no allocation allowed) -------
__device__ float g_q[Mc * DIMc];
__device__ float g_k[Mc * DIMc];
__device__ float g_v[Mc * DIMc];
__device__ float g_o[Mc * DIMc];
__device__ float g_cs[Sc * 32];
__device__ float g_sn[Sc * 32];
__device__ __nv_bfloat16 g_xhi[Mc * DIMc];
__device__ __nv_bfloat16 g_xlo[Mc * DIMc];
__device__ __nv_bfloat16 g_whi[4 * DIMc * DIMc];
__device__ __nv_bfloat16 g_wlo[4 * DIMc * DIMc];
__device__ __nv_bfloat16 g_ohi[Mc * DIMc];
__device__ __nv_bfloat16 g_olo[Mc * DIMc];

// ---------------- PTX helpers (non-'a' features only) -----------------------
__device__ __forceinline__ uint32_t smem_u32(const void* p) {
  uint32_t a;
  asm("{ .reg .u64 t; cvta.to.shared.u64 t, %1; cvt.u32.u64 %0, t; }"
      : "=r"(a) : "l"(p));
  return a;
}

__device__ __forceinline__ void cpa16(uint32_t dst, const void* src) {
  asm volatile("cp.async.ca.shared.global [%0], [%1], 16;" ::"r"(dst),
               "l"(src));
}
#define CP_COMMIT asm volatile("cp.async.commit_group;" ::: "memory")
#define CP_WAIT1 asm volatile("cp.async.wait_group 1;" ::: "memory")
#define CP_WAIT0 asm volatile("cp.async.wait_group 0;" ::: "memory")

__device__ __forceinline__ void ldm_x4(uint32_t addr, uint32_t* r) {
  asm volatile(
      "ldmatrix.sync.aligned.m8n8.x4.shared.b16 {%0,%1,%2,%3}, [%4];"
      : "=r"(r[0]), "=r"(r[1]), "=r"(r[2]), "=r"(r[3])
      : "r"(addr));
}

__device__ __forceinline__ void mma16816(float* c, const uint32_t* a,
                                         const uint32_t* b) {
  asm volatile(
      "mma.sync.aligned.m16n8k16.row.col.f32.bf16.bf16.f32 "
      "{%0,%1,%2,%3}, {%4,%5,%6,%7}, {%8,%9}, {%0,%1,%2,%3};"
      : "+f"(c[0]), "+f"(c[1]), "+f"(c[2]), "+f"(c[3])
      : "r"(a[0]), "r"(a[1]), "r"(a[2]), "r"(a[3]), "r"(b[0]), "r"(b[1]));
}

// ---------------- split kernels (fp32 -> bf16 hi/lo) ------------------------
__global__ void __launch_bounds__(256) split_kernel(
    const float* __restrict__ src, __nv_bfloat16* __restrict__ hi,
    __nv_bfloat16* __restrict__ lo, int n4) {
  int i = blockIdx.x * blockDim.x + threadIdx.x;
  if (i >= n4) return;
  float4 v = ((const float4*)src)[i];
  __nv_bfloat16 h0 = __float2bfloat16(v.x);
  __nv_bfloat16 h1 = __float2bfloat16(v.y);
  __nv_bfloat16 h2 = __float2bfloat16(v.z);
  __nv_bfloat16 h3 = __float2bfloat16(v.w);
  __nv_bfloat162* hp = (__nv_bfloat162*)hi;
  __nv_bfloat162* lp = (__nv_bfloat162*)lo;
  hp[2 * i] = __nv_bfloat162(h0, h1);
  hp[2 * i + 1] = __nv_bfloat162(h2, h3);
  lp[2 * i] = __nv_bfloat162(__float2bfloat16(v.x - __bfloat162float(h0)),
                             __float2bfloat16(v.y - __bfloat162float(h1)));
  lp[2 * i + 1] = __nv_bfloat162(__float2bfloat16(v.z - __bfloat162float(h2)),
                                 __float2bfloat16(v.w - __bfloat162float(h3)));
}

__global__ void __launch_bounds__(256) split_w_kernel(
    const float* __restrict__ Wq, const float* __restrict__ Wk,
    const float* __restrict__ Wv, const float* __restrict__ Wo) {
  int slot = blockIdx.y;
  const float* W = (slot == 0) ? Wq : (slot == 1) ? Wk : (slot == 2) ? Wv : Wo;
  int i = blockIdx.x * blockDim.x + threadIdx.x;
  int n4 = DIMc * DIMc / 4;
  if (i >= n4) return;
  float4 v = ((const float4*)W)[i];
  __nv_bfloat16* hi = g_whi + (size_t)slot * DIMc * DIMc;
  __nv_bfloat16* lo = g_wlo + (size_t)slot * DIMc * DIMc;
  __nv_bfloat16 h0 = __float2bfloat16(v.x);
  __nv_bfloat16 h1 = __float2bfloat16(v.y);
  __nv_bfloat16 h2 = __float2bfloat16(v.z);
  __nv_bfloat16 h3 = __float2bfloat16(v.w);
  __nv_bfloat162* hp = (__nv_bfloat162*)hi;
  __nv_bfloat162* lp = (__nv_bfloat162*)lo;
  hp[2 * i] = __nv_bfloat162(h0, h1);
  hp[2 * i + 1] = __nv_bfloat162(h2, h3);
  lp[2 * i] = __nv_bfloat162(__float2bfloat16(v.x - __bfloat162float(h0)),
                             __float2bfloat16(v.y - __bfloat162float(h1)));
  lp[2 * i + 1] = __nv_bfloat162(__float2bfloat16(v.z - __bfloat162float(h2)),
                                 __float2bfloat16(v.w - __bfloat162float(h3)));
}

// ---------------- HMMA split-bf16 GEMM --------------------------------------
// C[m][n] = sum_k A[m][k]*W[n][k] + bias[n].
// CTA tile 128x128, 8 warps (4x2), warp tile 32x64, k-chunk 32, cp.async 2-stage.
#define ASTRIDE_B 80                 // bytes per smem row (40 bf16)
#define TILE_B (128 * ASTRIDE_B)     // 10240 B per sub-tile
#define STAGE_B (4 * TILE_B)         // Ah,Al,Bh,Bl = 40960 B
#define G_SMEM (2 * STAGE_B)         // 81920 B

__device__ __forceinline__ void load_stage(
    uint32_t sbase, const __nv_bfloat16* __restrict__ Ahi,
    const __nv_bfloat16* __restrict__ Alo, const __nv_bfloat16* __restrict__ Bhi,
    const __nv_bfloat16* __restrict__ Blo, int row0, int col0, int k0,
    int tid) {
  const __nv_bfloat16* srcs[4];
  srcs[0] = Ahi + (size_t)row0 * DIMc;
  srcs[1] = Alo + (size_t)row0 * DIMc;
  srcs[2] = Bhi + (size_t)col0 * DIMc;
  srcs[3] = Blo + (size_t)col0 * DIMc;
#pragma unroll
  for (int tbl = 0; tbl < 4; tbl++) {
    const __nv_bfloat16* s = srcs[tbl];
    uint32_t dst = sbase + tbl * TILE_B;
#pragma unroll
    for (int it = 0; it < 2; it++) {
      int idx = tid + it * 256;
      int row = idx >> 2, c = idx & 3;
      cpa16(dst + row * ASTRIDE_B + c * 16,
            s + (size_t)row * DIMc + k0 + c * 8);
    }
  }
}

__device__ __forceinline__ void gemm_tc_body(
    const __nv_bfloat16* __restrict__ Ahi, const __nv_bfloat16* __restrict__ Alo,
    const __nv_bfloat16* __restrict__ Whi, const __nv_bfloat16* __restrict__ Wlo,
    const float* __restrict__ bias, float* __restrict__ C) {
  extern __shared__ char smg[];
  uint32_t sb = smem_u32(smg);
  const int tid = threadIdx.x;
  const int lane = tid & 31, wid = tid >> 5;
  const int warpm = wid & 3, warpn = wid >> 2;
  const int row0 = blockIdx.y * 128, col0 = blockIdx.x * 128;

  float acc[2][8][4];
#pragma unroll
  for (int mt = 0; mt < 2; mt++)
#pragma unroll
    for (int j = 0; j < 8; j++)
#pragma unroll
      for (int c = 0; c < 4; c++) acc[mt][j][c] = 0.f;

  // ldmatrix address components
  const int a_row = lane & 15, a_kof = (lane >> 4) * 8;          // A frag
  const int b_n = (lane & 7) + ((lane >> 4) * 8);                // B frag
  const int b_kof = ((lane >> 3) & 1) * 8;

  load_stage(sb, Ahi, Alo, Whi, Wlo, row0, col0, 0, tid);
  CP_COMMIT;

  const int T = DIMc / 32;  // 32 chunks
  for (int t = 0; t < T; t++) {
    if (t + 1 < T) {
      load_stage(sb + ((t + 1) & 1) * STAGE_B, Ahi, Alo, Whi, Wlo, row0, col0,
                 (t + 1) * 32, tid);
      CP_COMMIT;
      CP_WAIT1;
    } else {
      CP_WAIT0;
    }
    __syncthreads();

    uint32_t st = sb + (t & 1) * STAGE_B;
    uint32_t Ahs = st, Als = st + TILE_B, Bhs = st + 2 * TILE_B,
             Bls = st + 3 * TILE_B;
#pragma unroll
    for (int kk = 0; kk < 32; kk += 16) {
      uint32_t ah[2][4], al[2][4];
#pragma unroll
      for (int mt = 0; mt < 2; mt++) {
        int r = warpm * 32 + mt * 16 + a_row;
        uint32_t off = r * ASTRIDE_B + (kk + a_kof) * 2;
        ldm_x4(Ahs + off, ah[mt]);
        ldm_x4(Als + off, al[mt]);
      }
#pragma unroll
      for (int nt = 0; nt < 4; nt++) {
        uint32_t bh[4], bl[4];
        int n = warpn * 64 + nt * 16 + b_n;
        uint32_t off = n * ASTRIDE_B + (kk + b_kof) * 2;
        ldm_x4(Bhs + off, bh);
        ldm_x4(Bls + off, bl);
#pragma unroll
        for (int mt = 0; mt < 2; mt++) {
#pragma unroll
          for (int s2 = 0; s2 < 2; s2++) {
            float* cc = acc[mt][nt * 2 + s2];
            mma16816(cc, ah[mt], &bh[2 * s2]);
            mma16816(cc, ah[mt], &bl[2 * s2]);
            mma16816(cc, al[mt], &bh[2 * s2]);
          }
        }
      }
    }
    __syncthreads();
  }

  // Writeback with bias. m16n8 frag: c0,c1 -> row=lane/4, col=(lane%4)*2; c2,c3 -> row+8
#pragma unroll
  for (int mt = 0; mt < 2; mt++) {
#pragma unroll
    for (int j = 0; j < 8; j++) {
      int row = row0 + warpm * 32 + mt * 16 + (lane >> 2);
      int col = col0 + warpn * 64 + j * 8 + (lane & 3) * 2;
      float b0 = bias[col], b1 = bias[col + 1];
      float2 v0 = make_float2(acc[mt][j][0] + b0, acc[mt][j][1] + b1);
      float2 v1 = make_float2(acc[mt][j][2] + b0, acc[mt][j][3] + b1);
      *(float2*)(C + (size_t)row * DIMc + col) = v0;
      *(float2*)(C + (size_t)(row + 8) * DIMc + col) = v1;
    }
  }
}

__global__ void __launch_bounds__(256, 2) gemm_tc_qkv(
    const float* __restrict__ bq, const float* __restrict__ bk,
    const float* __restrict__ bv, float* __restrict__ Cq,
    float* __restrict__ Ck, float* __restrict__ Cv) {
  int z = blockIdx.z;
  const __nv_bfloat16* Whi = g_whi + (size_t)z * DIMc * DIMc;
  const __nv_bfloat16* Wlo = g_wlo + (size_t)z * DIMc * DIMc;
  const float* bias = (z == 0) ? bq : (z == 1) ? bk : bv;
  float* C = (z == 0) ? Cq : (z == 1) ? Ck : Cv;
  gemm_tc_body(g_xhi, g_xlo, Whi, Wlo, bias, C);
}

__global__ void __launch_bounds__(256, 2) gemm_tc_out(
    const float* __restrict__ bo, float* __restrict__ C) {
  const __nv_bfloat16* Whi = g_whi + (size_t)3 * DIMc * DIMc;
  const __nv_bfloat16* Wlo = g_wlo + (size_t)3 * DIMc * DIMc;
  gemm_tc_body(g_ohi, g_olo, Whi, Wlo, bo, C);
}

// ---------------- RoPE ------------------------------------------------------
__global__ void rope_table_kernel() {
  int idx = blockIdx.x * blockDim.x + threadIdx.x;
  if (idx >= Sc * 32) return;
  int j = idx & 31;
  int s = idx >> 5;
  double freq = exp(-(double)j * (log(10000.0) / 32.0));
  double ang = (double)s * freq;
  g_cs[idx] = (float)cos(ang);
  g_sn[idx] = (float)sin(ang);
}

__global__ void __launch_bounds__(256) rope_apply_kernel(float* __restrict__ q,
                                                         float* __restrict__ k) {
  int idx = blockIdx.x * blockDim.x + threadIdx.x;
  if (idx >= Mc * Hc * 32) return;
  int j = idx & 31;
  int h = (idx >> 5) & (Hc - 1);
  int m = idx >> 9;
  int s = m & (Sc - 1);
  float cs = g_cs[s * 32 + j];
  float sn = g_sn[s * 32 + j];
  size_t base = (size_t)m * DIMc + h * DHc;
  float q1 = q[base + j], q2 = q[base + j + 32];
  q[base + j] = fmaf(q1, cs, -q2 * sn);
  q[base + j + 32] = fmaf(q2, cs, q1 * sn);
  float k1 = k[base + j], k2 = k[base + j + 32];
  k[base + j] = fmaf(k1, cs, -k2 * sn);
  k[base + j + 32] = fmaf(k2, cs, k1 * sn);
}

// ---------------- Flash attention (R2 measured-good version) ----------------
#define FPAD 68
__global__ void __launch_bounds__(256) flash_kernel(
    const float* __restrict__ q, const float* __restrict__ k,
    const float* __restrict__ v, float* __restrict__ o) {
  extern __shared__ float sm[];
  float* Qs = sm;
  float* Ks = Qs + 64 * FPAD;
  float* Vs = Ks + 64 * FPAD;
  float* Ps = Vs + 64 * FPAD;

  const int tid = threadIdx.x;
  const int tx = tid & 15, ty = tid >> 4;
  const int bh = blockIdx.y;
  const int b = bh >> 4, h = bh & 15;
  const int q0 = blockIdx.x * 64;
  const float* qb = q + (size_t)b * Sc * DIMc + h * DHc;
  const float* kb = k + (size_t)b * Sc * DIMc + h * DHc;
  const float* vb = v + (size_t)b * Sc * DIMc + h * DHc;

  for (int idx = tid; idx < 64 * 16; idx += 256) {
    int i = idx >> 4, d4 = (idx & 15) * 4;
    float4 t4 = *(const float4*)(qb + (size_t)(q0 + i) * DIMc + d4);
    Qs[(d4 + 0) * FPAD + i] = t4.x;
    Qs[(d4 + 1) * FPAD + i] = t4.y;
    Qs[(d4 + 2) * FPAD + i] = t4.z;
    Qs[(d4 + 3) * FPAD + i] = t4.w;
  }

  float m_i[4], l_i[4], acc[4][4];
#pragma unroll
  for (int r = 0; r < 4; r++) {
    m_i[r] = -INFINITY;
    l_i[r] = 0.f;
#pragma unroll
    for (int c = 0; c < 4; c++) acc[r][c] = 0.f;
  }

  const float scale = 0.125f;

  for (int t = 0; t < 16; t++) {
    int kv0 = t * 64;
    __syncthreads();
    for (int idx = tid; idx < 64 * 16; idx += 256) {
      int j = idx >> 4, d4 = (idx & 15) * 4;
      float4 t4 = *(const float4*)(kb + (size_t)(kv0 + j) * DIMc + d4);
      Ks[(d4 + 0) * FPAD + j] = t4.x;
      Ks[(d4 + 1) * FPAD + j] = t4.y;
      Ks[(d4 + 2) * FPAD + j] = t4.z;
      Ks[(d4 + 3) * FPAD + j] = t4.w;
      float4 v4 = *(const float4*)(vb + (size_t)(kv0 + j) * DIMc + d4);
      *(float4*)(Vs + j * FPAD + d4) = v4;
    }
    __syncthreads();

    float s[4][4];
#pragma unroll
    for (int r = 0; r < 4; r++)
#pragma unroll
      for (int c = 0; c < 4; c++) s[r][c] = 0.f;
#pragma unroll 16
    for (int d = 0; d < 64; d++) {
      float4 a = *(const float4*)&Qs[d * FPAD + ty * 4];
      float4 bb = *(const float4*)&Ks[d * FPAD + tx * 4];
      float ar[4] = {a.x, a.y, a.z, a.w};
      float br[4] = {bb.x, bb.y, bb.z, bb.w};
#pragma unroll
      for (int r = 0; r < 4; r++)
#pragma unroll
        for (int c = 0; c < 4; c++) s[r][c] = fmaf(ar[r], br[c], s[r][c]);
    }

#pragma unroll
    for (int r = 0; r < 4; r++) {
#pragma unroll
      for (int c = 0; c < 4; c++) s[r][c] *= scale;
      float mx = fmaxf(fmaxf(s[r][0], s[r][1]), fmaxf(s[r][2], s[r][3]));
#pragma unroll
      for (int off = 8; off > 0; off >>= 1)
        mx = fmaxf(mx, __shfl_xor_sync(0xffffffffu, mx, off));
      float mn = fmaxf(m_i[r], mx);
      float corr = __expf(m_i[r] - mn);
      float rs = 0.f;
#pragma unroll
      for (int c = 0; c < 4; c++) {
        float p = __expf(s[r][c] - mn);
        rs += p;
        Ps[(tx * 4 + c) * FPAD + ty * 4 + r] = p;
      }
#pragma unroll
      for (int off = 8; off > 0; off >>= 1)
        rs += __shfl_xor_sync(0xffffffffu, rs, off);
      l_i[r] = l_i[r] * corr + rs;
      m_i[r] = mn;
#pragma unroll
      for (int c = 0; c < 4; c++) acc[r][c] *= corr;
    }
    __syncthreads();

#pragma unroll 16
    for (int j = 0; j < 64; j++) {
      float4 a = *(const float4*)&Ps[j * FPAD + ty * 4];
      float4 bv = *(const float4*)&Vs[j * FPAD + tx * 4];
      float ar[4] = {a.x, a.y, a.z, a.w};
      float br[4] = {bv.x, bv.y, bv.z, bv.w};
#pragma unroll
      for (int r = 0; r < 4; r++)
#pragma unroll
        for (int c = 0; c < 4; c++) acc[r][c] = fmaf(ar[r], br[c], acc[r][c]);
    }
  }

#pragma unroll
  for (int r = 0; r < 4; r++) {
    float inv = 1.f / l_i[r];
    float4 ov = make_float4(acc[r][0] * inv, acc[r][1] * inv, acc[r][2] * inv,
                            acc[r][3] * inv);
    *(float4*)(o + (size_t)(b * Sc + q0 + ty * 4 + r) * DIMc + h * DHc +
               tx * 4) = ov;
  }
}

// ----------------------------------------------------------------------------
extern "C" void kernel_launch(void* const* d_in, const int* in_sizes, int n_in,
                              void* d_out, int out_size) {
  const float* x = (const float*)d_in[0];
  const float* Wq = (const float*)d_in[1];
  const float* bq = (const float*)d_in[2];
  const float* Wk = (const float*)d_in[3];
  const float* bk = (const float*)d_in[4];
  const float* Wv = (const float*)d_in[5];
  const float* bv = (const float*)d_in[6];
  const float* Wo = (const float*)d_in[7];
  const float* bo = (const float*)d_in[8];
  float* out = (float*)d_out;

  float *qp, *kp, *vp, *op;
  cudaGetSymbolAddress((void**)&qp, g_q);
  cudaGetSymbolAddress((void**)&kp, g_k);
  cudaGetSymbolAddress((void**)&vp, g_v);
  cudaGetSymbolAddress((void**)&op, g_o);
  __nv_bfloat16 *xhi, *xlo, *ohi, *olo;
  cudaGetSymbolAddress((void**)&xhi, g_xhi);
  cudaGetSymbolAddress((void**)&xlo, g_xlo);
  cudaGetSymbolAddress((void**)&ohi, g_ohi);
  cudaGetSymbolAddress((void**)&olo, g_olo);

  cudaFuncSetAttribute(gemm_tc_qkv, cudaFuncAttributeMaxDynamicSharedMemorySize,
                       G_SMEM);
  cudaFuncSetAttribute(gemm_tc_out, cudaFuncAttributeMaxDynamicSharedMemorySize,
                       G_SMEM);
  size_t fshm = 4 * 64 * FPAD * sizeof(float);
  cudaFuncSetAttribute(flash_kernel, cudaFuncAttributeMaxDynamicSharedMemorySize,
                       (int)fshm);

  rope_table_kernel<<<(Sc * 32 + 255) / 256, 256>>>();

  int n4x = Mc * DIMc / 4;
  split_kernel<<<(n4x + 255) / 256, 256>>>(x, xhi, xlo, n4x);
  int n4w = DIMc * DIMc / 4;
  split_w_kernel<<<dim3((n4w + 255) / 256, 4), 256>>>(Wq, Wk, Wv, Wo);

  gemm_tc_qkv<<<dim3(DIMc / 128, Mc / 128, 3), 256, G_SMEM>>>(bq, bk, bv, qp,
                                                              kp, vp);

  int total = Mc * Hc * 32;
  rope_apply_kernel<<<(total + 255) / 256, 256>>>(qp, kp);

  flash_kernel<<<dim3(Sc / 64, Bc * Hc), 256, fshm>>>(qp, kp, vp, op);

  split_kernel<<<(n4x + 255) / 256, 256>>>(op, ohi, olo, n4x);
  gemm_tc_out<<<dim3(DIMc / 128, Mc / 128), 256, G_SMEM>>>(bo, out);
}

// round 7
// speedup vs baseline: 2.5155x; 1.4600x over previous
#include <cuda_runtime.h>
#include <cuda_bf16.h>
#include <math.h>
#include <stdint.h>

#define Bc 4
#define Sc 1024
#define DIMc 1024
#define Hc 16
#define DHc 64
#define Mc (Bc * Sc)

// ---------------- scratch (__device__ globals; no allocation allowed) -------
__device__ float g_q[Mc * DIMc];
__device__ float g_k[Mc * DIMc];
__device__ float g_v[Mc * DIMc];
__device__ float g_o[Mc * DIMc];
__device__ float g_cs[Sc * 32];
__device__ float g_sn[Sc * 32];
__device__ __nv_bfloat16 g_xhi[Mc * DIMc];
__device__ __nv_bfloat16 g_xlo[Mc * DIMc];
__device__ __nv_bfloat16 g_whi[4 * DIMc * DIMc];
__device__ __nv_bfloat16 g_wlo[4 * DIMc * DIMc];
__device__ __nv_bfloat16 g_ohi[Mc * DIMc];
__device__ __nv_bfloat16 g_olo[Mc * DIMc];

// ---------------- PTX helpers (non-'a' features only) -----------------------
__device__ __forceinline__ uint32_t smem_u32(const void* p) {
  uint32_t a;
  asm("{ .reg .u64 t; cvta.to.shared.u64 t, %1; cvt.u32.u64 %0, t; }"
      : "=r"(a) : "l"(p));
  return a;
}

__device__ __forceinline__ void cpa16(uint32_t dst, const void* src) {
  asm volatile("cp.async.ca.shared.global [%0], [%1], 16;" ::"r"(dst),
               "l"(src));
}
#define CP_COMMIT asm volatile("cp.async.commit_group;" ::: "memory")
#define CP_WAIT1 asm volatile("cp.async.wait_group 1;" ::: "memory")
#define CP_WAIT0 asm volatile("cp.async.wait_group 0;" ::: "memory")

__device__ __forceinline__ void ldm_x4(uint32_t addr, uint32_t* r) {
  asm volatile(
      "ldmatrix.sync.aligned.m8n8.x4.shared.b16 {%0,%1,%2,%3}, [%4];"
      : "=r"(r[0]), "=r"(r[1]), "=r"(r[2]), "=r"(r[3])
      : "r"(addr));
}

__device__ __forceinline__ void mma16816(float* c, const uint32_t* a,
                                         const uint32_t* b) {
  asm volatile(
      "mma.sync.aligned.m16n8k16.row.col.f32.bf16.bf16.f32 "
      "{%0,%1,%2,%3}, {%4,%5,%6,%7}, {%8,%9}, {%0,%1,%2,%3};"
      : "+f"(c[0]), "+f"(c[1]), "+f"(c[2]), "+f"(c[3])
      : "r"(a[0]), "r"(a[1]), "r"(a[2]), "r"(a[3]), "r"(b[0]), "r"(b[1]));
}

__device__ __forceinline__ uint32_t packbf(float a, float b) {
  __nv_bfloat162 t(__float2bfloat16(a), __float2bfloat16(b));
  return *(uint32_t*)&t;
}

// ---------------- split kernels (fp32 -> bf16 hi/lo) ------------------------
__global__ void __launch_bounds__(256) split_kernel(
    const float* __restrict__ src, __nv_bfloat16* __restrict__ hi,
    __nv_bfloat16* __restrict__ lo, int n4) {
  int i = blockIdx.x * blockDim.x + threadIdx.x;
  if (i >= n4) return;
  float4 v = ((const float4*)src)[i];
  __nv_bfloat16 h0 = __float2bfloat16(v.x);
  __nv_bfloat16 h1 = __float2bfloat16(v.y);
  __nv_bfloat16 h2 = __float2bfloat16(v.z);
  __nv_bfloat16 h3 = __float2bfloat16(v.w);
  __nv_bfloat162* hp = (__nv_bfloat162*)hi;
  __nv_bfloat162* lp = (__nv_bfloat162*)lo;
  hp[2 * i] = __nv_bfloat162(h0, h1);
  hp[2 * i + 1] = __nv_bfloat162(h2, h3);
  lp[2 * i] = __nv_bfloat162(__float2bfloat16(v.x - __bfloat162float(h0)),
                             __float2bfloat16(v.y - __bfloat162float(h1)));
  lp[2 * i + 1] = __nv_bfloat162(__float2bfloat16(v.z - __bfloat162float(h2)),
                                 __float2bfloat16(v.w - __bfloat162float(h3)));
}

__global__ void __launch_bounds__(256) split_w_kernel(
    const float* __restrict__ Wq, const float* __restrict__ Wk,
    const float* __restrict__ Wv, const float* __restrict__ Wo) {
  int slot = blockIdx.y;
  const float* W = (slot == 0) ? Wq : (slot == 1) ? Wk : (slot == 2) ? Wv : Wo;
  int i = blockIdx.x * blockDim.x + threadIdx.x;
  int n4 = DIMc * DIMc / 4;
  if (i >= n4) return;
  float4 v = ((const float4*)W)[i];
  __nv_bfloat16* hi = g_whi + (size_t)slot * DIMc * DIMc;
  __nv_bfloat16* lo = g_wlo + (size_t)slot * DIMc * DIMc;
  __nv_bfloat16 h0 = __float2bfloat16(v.x);
  __nv_bfloat16 h1 = __float2bfloat16(v.y);
  __nv_bfloat16 h2 = __float2bfloat16(v.z);
  __nv_bfloat16 h3 = __float2bfloat16(v.w);
  __nv_bfloat162* hp = (__nv_bfloat162*)hi;
  __nv_bfloat162* lp = (__nv_bfloat162*)lo;
  hp[2 * i] = __nv_bfloat162(h0, h1);
  hp[2 * i + 1] = __nv_bfloat162(h2, h3);
  lp[2 * i] = __nv_bfloat162(__float2bfloat16(v.x - __bfloat162float(h0)),
                             __float2bfloat16(v.y - __bfloat162float(h1)));
  lp[2 * i + 1] = __nv_bfloat162(__float2bfloat16(v.z - __bfloat162float(h2)),
                                 __float2bfloat16(v.w - __bfloat162float(h3)));
}

// ---------------- HMMA split-bf16 GEMM (unchanged, measured 341 TF/s) -------
#define ASTRIDE_B 80
#define TILE_B (128 * ASTRIDE_B)
#define STAGE_B (4 * TILE_B)
#define G_SMEM (2 * STAGE_B)

__device__ __forceinline__ void load_stage(
    uint32_t sbase, const __nv_bfloat16* __restrict__ Ahi,
    const __nv_bfloat16* __restrict__ Alo, const __nv_bfloat16* __restrict__ Bhi,
    const __nv_bfloat16* __restrict__ Blo, int row0, int col0, int k0,
    int tid) {
  const __nv_bfloat16* srcs[4];
  srcs[0] = Ahi + (size_t)row0 * DIMc;
  srcs[1] = Alo + (size_t)row0 * DIMc;
  srcs[2] = Bhi + (size_t)col0 * DIMc;
  srcs[3] = Blo + (size_t)col0 * DIMc;
#pragma unroll
  for (int tbl = 0; tbl < 4; tbl++) {
    const __nv_bfloat16* s = srcs[tbl];
    uint32_t dst = sbase + tbl * TILE_B;
#pragma unroll
    for (int it = 0; it < 2; it++) {
      int idx = tid + it * 256;
      int row = idx >> 2, c = idx & 3;
      cpa16(dst + row * ASTRIDE_B + c * 16,
            s + (size_t)row * DIMc + k0 + c * 8);
    }
  }
}

__device__ __forceinline__ void gemm_tc_body(
    const __nv_bfloat16* __restrict__ Ahi, const __nv_bfloat16* __restrict__ Alo,
    const __nv_bfloat16* __restrict__ Whi, const __nv_bfloat16* __restrict__ Wlo,
    const float* __restrict__ bias, float* __restrict__ C) {
  extern __shared__ char smg[];
  uint32_t sb = smem_u32(smg);
  const int tid = threadIdx.x;
  const int lane = tid & 31, wid = tid >> 5;
  const int warpm = wid & 3, warpn = wid >> 2;
  const int row0 = blockIdx.y * 128, col0 = blockIdx.x * 128;

  float acc[2][8][4];
#pragma unroll
  for (int mt = 0; mt < 2; mt++)
#pragma unroll
    for (int j = 0; j < 8; j++)
#pragma unroll
      for (int c = 0; c < 4; c++) acc[mt][j][c] = 0.f;

  const int a_row = lane & 15, a_kof = (lane >> 4) * 8;
  const int b_n = (lane & 7) + ((lane >> 4) * 8);
  const int b_kof = ((lane >> 3) & 1) * 8;

  load_stage(sb, Ahi, Alo, Whi, Wlo, row0, col0, 0, tid);
  CP_COMMIT;

  const int T = DIMc / 32;
  for (int t = 0; t < T; t++) {
    if (t + 1 < T) {
      load_stage(sb + ((t + 1) & 1) * STAGE_B, Ahi, Alo, Whi, Wlo, row0, col0,
                 (t + 1) * 32, tid);
      CP_COMMIT;
      CP_WAIT1;
    } else {
      CP_WAIT0;
    }
    __syncthreads();

    uint32_t st = sb + (t & 1) * STAGE_B;
    uint32_t Ahs = st, Als = st + TILE_B, Bhs = st + 2 * TILE_B,
             Bls = st + 3 * TILE_B;
#pragma unroll
    for (int kk = 0; kk < 32; kk += 16) {
      uint32_t ah[2][4], al[2][4];
#pragma unroll
      for (int mt = 0; mt < 2; mt++) {
        int r = warpm * 32 + mt * 16 + a_row;
        uint32_t off = r * ASTRIDE_B + (kk + a_kof) * 2;
        ldm_x4(Ahs + off, ah[mt]);
        ldm_x4(Als + off, al[mt]);
      }
#pragma unroll
      for (int nt = 0; nt < 4; nt++) {
        uint32_t bh[4], bl[4];
        int n = warpn * 64 + nt * 16 + b_n;
        uint32_t off = n * ASTRIDE_B + (kk + b_kof) * 2;
        ldm_x4(Bhs + off, bh);
        ldm_x4(Bls + off, bl);
#pragma unroll
        for (int mt = 0; mt < 2; mt++) {
#pragma unroll
          for (int s2 = 0; s2 < 2; s2++) {
            float* cc = acc[mt][nt * 2 + s2];
            mma16816(cc, ah[mt], &bh[2 * s2]);
            mma16816(cc, ah[mt], &bl[2 * s2]);
            mma16816(cc, al[mt], &bh[2 * s2]);
          }
        }
      }
    }
    __syncthreads();
  }

#pragma unroll
  for (int mt = 0; mt < 2; mt++) {
#pragma unroll
    for (int j = 0; j < 8; j++) {
      int row = row0 + warpm * 32 + mt * 16 + (lane >> 2);
      int col = col0 + warpn * 64 + j * 8 + (lane & 3) * 2;
      float b0 = bias[col], b1 = bias[col + 1];
      float2 v0 = make_float2(acc[mt][j][0] + b0, acc[mt][j][1] + b1);
      float2 v1 = make_float2(acc[mt][j][2] + b0, acc[mt][j][3] + b1);
      *(float2*)(C + (size_t)row * DIMc + col) = v0;
      *(float2*)(C + (size_t)(row + 8) * DIMc + col) = v1;
    }
  }
}

__global__ void __launch_bounds__(256, 2) gemm_tc_qkv(
    const float* __restrict__ bq, const float* __restrict__ bk,
    const float* __restrict__ bv, float* __restrict__ Cq,
    float* __restrict__ Ck, float* __restrict__ Cv) {
  int z = blockIdx.z;
  const __nv_bfloat16* Whi = g_whi + (size_t)z * DIMc * DIMc;
  const __nv_bfloat16* Wlo = g_wlo + (size_t)z * DIMc * DIMc;
  const float* bias = (z == 0) ? bq : (z == 1) ? bk : bv;
  float* C = (z == 0) ? Cq : (z == 1) ? Ck : Cv;
  gemm_tc_body(g_xhi, g_xlo, Whi, Wlo, bias, C);
}

__global__ void __launch_bounds__(256, 2) gemm_tc_out(
    const float* __restrict__ bo, float* __restrict__ C) {
  const __nv_bfloat16* Whi = g_whi + (size_t)3 * DIMc * DIMc;
  const __nv_bfloat16* Wlo = g_wlo + (size_t)3 * DIMc * DIMc;
  gemm_tc_body(g_ohi, g_olo, Whi, Wlo, bo, C);
}

// ---------------- RoPE ------------------------------------------------------
__global__ void rope_table_kernel() {
  int idx = blockIdx.x * blockDim.x + threadIdx.x;
  if (idx >= Sc * 32) return;
  int j = idx & 31;
  int s = idx >> 5;
  double freq = exp(-(double)j * (log(10000.0) / 32.0));
  double ang = (double)s * freq;
  g_cs[idx] = (float)cos(ang);
  g_sn[idx] = (float)sin(ang);
}

__global__ void __launch_bounds__(256) rope_apply_kernel(float* __restrict__ q,
                                                         float* __restrict__ k) {
  int idx = blockIdx.x * blockDim.x + threadIdx.x;
  if (idx >= Mc * Hc * 32) return;
  int j = idx & 31;
  int h = (idx >> 5) & (Hc - 1);
  int m = idx >> 9;
  int s = m & (Sc - 1);
  float cs = g_cs[s * 32 + j];
  float sn = g_sn[s * 32 + j];
  size_t base = (size_t)m * DIMc + h * DHc;
  float q1 = q[base + j], q2 = q[base + j + 32];
  q[base + j] = fmaf(q1, cs, -q2 * sn);
  q[base + j + 32] = fmaf(q2, cs, q1 * sn);
  float k1 = k[base + j], k2 = k[base + j + 32];
  k[base + j] = fmaf(k1, cs, -k2 * sn);
  k[base + j + 32] = fmaf(k2, cs, k1 * sn);
}

// ---------------- Flash attention, HMMA split-bf16 (FA2 layout) -------------
// Block: 128 q-rows x one (b,h). 8 warps, 16 q rows each. KV tile = 64.
// smem rows padded to 72 bf16 (144 B) -> conflict-free ldmatrix.
#define FSTR 72
#define F_QH 0
#define F_QL 9216
#define F_KH 18432
#define F_KL 23040
#define F_VH 27648
#define F_VL 32256
#define F_SMEM_B (36864 * 2)

__global__ void __launch_bounds__(256) flash_tc_kernel(
    const float* __restrict__ q, const float* __restrict__ k,
    const float* __restrict__ v, float* __restrict__ o) {
  extern __shared__ __nv_bfloat16 sf[];
  uint32_t sbase = smem_u32(sf);
  const uint32_t QhA = sbase + F_QH * 2, QlA = sbase + F_QL * 2;
  const uint32_t KhA = sbase + F_KH * 2, KlA = sbase + F_KL * 2;
  const uint32_t VhA = sbase + F_VH * 2, VlA = sbase + F_VL * 2;

  const int tid = threadIdx.x, lane = tid & 31, w = tid >> 5;
  const int b = blockIdx.y >> 4, h = blockIdx.y & 15;
  const int q0 = blockIdx.x * 128;
  const float* qb = q + (size_t)b * Sc * DIMc + h * DHc;
  const float* kb = k + (size_t)b * Sc * DIMc + h * DHc;
  const float* vb = v + (size_t)b * Sc * DIMc + h * DHc;

  // Load Q tile 128x64, split hi/lo
#pragma unroll
  for (int it = 0; it < 8; it++) {
    int idx = tid + it * 256;
    int i = idx >> 4, d4 = (idx & 15) * 4;
    float4 t4 = *(const float4*)(qb + (size_t)(q0 + i) * DIMc + d4);
    float vv[4] = {t4.x, t4.y, t4.z, t4.w};
#pragma unroll
    for (int e = 0; e < 4; e++) {
      __nv_bfloat16 hh = __float2bfloat16(vv[e]);
      sf[F_QH + i * FSTR + d4 + e] = hh;
      sf[F_QL + i * FSTR + d4 + e] =
          __float2bfloat16(vv[e] - __bfloat162float(hh));
    }
  }
  __syncthreads();

  // Resident Q fragments (4 k-chunks of 16)
  const int a_row = lane & 15, a_kof = (lane >> 4) * 8;
  const int b_n = (lane & 7) + ((lane >> 4) * 8);
  const int b_kof = ((lane >> 3) & 1) * 8;
  uint32_t qh[4][4], ql[4][4];
#pragma unroll
  for (int kc = 0; kc < 4; kc++) {
    uint32_t off = (uint32_t)(w * 16 + a_row) * (FSTR * 2) +
                   (kc * 16 + a_kof) * 2;
    ldm_x4(QhA + off, qh[kc]);
    ldm_x4(QlA + off, ql[kc]);
  }

  float m0 = -INFINITY, m1 = -INFINITY, l0 = 0.f, l1 = 0.f;
  float acc[8][4];
#pragma unroll
  for (int dt = 0; dt < 8; dt++)
#pragma unroll
    for (int c = 0; c < 4; c++) acc[dt][c] = 0.f;

  const float scale = 0.125f;

  for (int t = 0; t < 16; t++) {
    int kv0 = t * 64;
    __syncthreads();  // previous tile's ldmatrix readers done
    // Load K (64x64, rows j) and V transposed (rows d), split hi/lo
#pragma unroll
    for (int it = 0; it < 4; it++) {
      int idx = tid + it * 256;
      int j = idx >> 4, d4 = (idx & 15) * 4;
      float4 kk = *(const float4*)(kb + (size_t)(kv0 + j) * DIMc + d4);
      float kvv[4] = {kk.x, kk.y, kk.z, kk.w};
#pragma unroll
      for (int e = 0; e < 4; e++) {
        __nv_bfloat16 hh = __float2bfloat16(kvv[e]);
        sf[F_KH + j * FSTR + d4 + e] = hh;
        sf[F_KL + j * FSTR + d4 + e] =
            __float2bfloat16(kvv[e] - __bfloat162float(hh));
      }
      float4 vv4 = *(const float4*)(vb + (size_t)(kv0 + j) * DIMc + d4);
      float vvv[4] = {vv4.x, vv4.y, vv4.z, vv4.w};
#pragma unroll
      for (int e = 0; e < 4; e++) {
        __nv_bfloat16 hh = __float2bfloat16(vvv[e]);
        sf[F_VH + (d4 + e) * FSTR + j] = hh;
        sf[F_VL + (d4 + e) * FSTR + j] =
            __float2bfloat16(vvv[e] - __bfloat162float(hh));
      }
    }
    __syncthreads();

    // ---- S = Q K^T (warp: 16 x 64), split 3-product
    float s[8][4];
#pragma unroll
    for (int nt = 0; nt < 8; nt++)
#pragma unroll
      for (int c = 0; c < 4; c++) s[nt][c] = 0.f;
#pragma unroll
    for (int kc = 0; kc < 4; kc++) {
#pragma unroll
      for (int ng = 0; ng < 4; ng++) {
        uint32_t bh4[4], bl4[4];
        uint32_t off = (uint32_t)(ng * 16 + b_n) * (FSTR * 2) +
                       (kc * 16 + b_kof) * 2;
        ldm_x4(KhA + off, bh4);
        ldm_x4(KlA + off, bl4);
#pragma unroll
        for (int s2 = 0; s2 < 2; s2++) {
          float* cc = s[ng * 2 + s2];
          mma16816(cc, qh[kc], &bh4[2 * s2]);
          mma16816(cc, qh[kc], &bl4[2 * s2]);
          mma16816(cc, ql[kc], &bh4[2 * s2]);
        }
      }
    }

    // ---- online softmax (rows r0 = lane>>2 and r0+8)
    float mx0 = -INFINITY, mx1 = -INFINITY;
#pragma unroll
    for (int nt = 0; nt < 8; nt++) {
      s[nt][0] *= scale; s[nt][1] *= scale;
      s[nt][2] *= scale; s[nt][3] *= scale;
      mx0 = fmaxf(mx0, fmaxf(s[nt][0], s[nt][1]));
      mx1 = fmaxf(mx1, fmaxf(s[nt][2], s[nt][3]));
    }
    mx0 = fmaxf(mx0, __shfl_xor_sync(0xffffffffu, mx0, 1));
    mx0 = fmaxf(mx0, __shfl_xor_sync(0xffffffffu, mx0, 2));
    mx1 = fmaxf(mx1, __shfl_xor_sync(0xffffffffu, mx1, 1));
    mx1 = fmaxf(mx1, __shfl_xor_sync(0xffffffffu, mx1, 2));
    float mn0 = fmaxf(m0, mx0), mn1 = fmaxf(m1, mx1);
    float corr0 = __expf(m0 - mn0), corr1 = __expf(m1 - mn1);
    m0 = mn0; m1 = mn1;
    float rs0 = 0.f, rs1 = 0.f;
#pragma unroll
    for (int nt = 0; nt < 8; nt++) {
      s[nt][0] = __expf(s[nt][0] - mn0);
      s[nt][1] = __expf(s[nt][1] - mn0);
      s[nt][2] = __expf(s[nt][2] - mn1);
      s[nt][3] = __expf(s[nt][3] - mn1);
      rs0 += s[nt][0] + s[nt][1];
      rs1 += s[nt][2] + s[nt][3];
    }
    rs0 += __shfl_xor_sync(0xffffffffu, rs0, 1);
    rs0 += __shfl_xor_sync(0xffffffffu, rs0, 2);
    rs1 += __shfl_xor_sync(0xffffffffu, rs1, 1);
    rs1 += __shfl_xor_sync(0xffffffffu, rs1, 2);
    l0 = l0 * corr0 + rs0;
    l1 = l1 * corr1 + rs1;

    // P hi/lo fragments: j-chunk kc uses S n-tiles 2kc, 2kc+1
    uint32_t ph[4][4], pl[4][4];
#pragma unroll
    for (int kc = 0; kc < 4; kc++) {
      float* sa = s[2 * kc];
      float* sbn = s[2 * kc + 1];
      float r0a = __bfloat162float(__float2bfloat16(sa[0]));
      float r0b = __bfloat162float(__float2bfloat16(sa[1]));
      float r1a = __bfloat162float(__float2bfloat16(sa[2]));
      float r1b = __bfloat162float(__float2bfloat16(sa[3]));
      float n0a = __bfloat162float(__float2bfloat16(sbn[0]));
      float n0b = __bfloat162float(__float2bfloat16(sbn[1]));
      float n1a = __bfloat162float(__float2bfloat16(sbn[2]));
      float n1b = __bfloat162float(__float2bfloat16(sbn[3]));
      ph[kc][0] = packbf(sa[0], sa[1]);
      ph[kc][1] = packbf(sa[2], sa[3]);
      ph[kc][2] = packbf(sbn[0], sbn[1]);
      ph[kc][3] = packbf(sbn[2], sbn[3]);
      pl[kc][0] = packbf(sa[0] - r0a, sa[1] - r0b);
      pl[kc][1] = packbf(sa[2] - r1a, sa[3] - r1b);
      pl[kc][2] = packbf(sbn[0] - n0a, sbn[1] - n0b);
      pl[kc][3] = packbf(sbn[2] - n1a, sbn[3] - n1b);
    }

    // rescale O acc
#pragma unroll
    for (int dt = 0; dt < 8; dt++) {
      acc[dt][0] *= corr0; acc[dt][1] *= corr0;
      acc[dt][2] *= corr1; acc[dt][3] *= corr1;
    }

    // ---- O += P V (warp: 16 x 64)
#pragma unroll
    for (int kc = 0; kc < 4; kc++) {
#pragma unroll
      for (int ng = 0; ng < 4; ng++) {
        uint32_t vh4[4], vl4[4];
        uint32_t off = (uint32_t)(ng * 16 + b_n) * (FSTR * 2) +
                       (kc * 16 + b_kof) * 2;
        ldm_x4(VhA + off, vh4);
        ldm_x4(VlA + off, vl4);
#pragma unroll
        for (int s2 = 0; s2 < 2; s2++) {
          float* cc = acc[ng * 2 + s2];
          mma16816(cc, ph[kc], &vh4[2 * s2]);
          mma16816(cc, ph[kc], &vl4[2 * s2]);
          mma16816(cc, pl[kc], &vh4[2 * s2]);
        }
      }
    }
  }

  // Writeback
  float inv0 = 1.f / l0, inv1 = 1.f / l1;
  int r0 = q0 + w * 16 + (lane >> 2);
#pragma unroll
  for (int dt = 0; dt < 8; dt++) {
    int col = h * DHc + dt * 8 + (lane & 3) * 2;
    float2 v0 = make_float2(acc[dt][0] * inv0, acc[dt][1] * inv0);
    float2 v1 = make_float2(acc[dt][2] * inv1, acc[dt][3] * inv1);
    *(float2*)(o + (size_t)(b * Sc + r0) * DIMc + col) = v0;
    *(float2*)(o + (size_t)(b * Sc + r0 + 8) * DIMc + col) = v1;
  }
}

// ----------------------------------------------------------------------------
extern "C" void kernel_launch(void* const* d_in, const int* in_sizes, int n_in,
                              void* d_out, int out_size) {
  const float* x = (const float*)d_in[0];
  const float* Wq = (const float*)d_in[1];
  const float* bq = (const float*)d_in[2];
  const float* Wk = (const float*)d_in[3];
  const float* bk = (const float*)d_in[4];
  const float* Wv = (const float*)d_in[5];
  const float* bv = (const float*)d_in[6];
  const float* Wo = (const float*)d_in[7];
  const float* bo = (const float*)d_in[8];
  float* out = (float*)d_out;

  float *qp, *kp, *vp, *op;
  cudaGetSymbolAddress((void**)&qp, g_q);
  cudaGetSymbolAddress((void**)&kp, g_k);
  cudaGetSymbolAddress((void**)&vp, g_v);
  cudaGetSymbolAddress((void**)&op, g_o);
  __nv_bfloat16 *xhi, *xlo, *ohi, *olo;
  cudaGetSymbolAddress((void**)&xhi, g_xhi);
  cudaGetSymbolAddress((void**)&xlo, g_xlo);
  cudaGetSymbolAddress((void**)&ohi, g_ohi);
  cudaGetSymbolAddress((void**)&olo, g_olo);

  cudaFuncSetAttribute(gemm_tc_qkv, cudaFuncAttributeMaxDynamicSharedMemorySize,
                       G_SMEM);
  cudaFuncSetAttribute(gemm_tc_out, cudaFuncAttributeMaxDynamicSharedMemorySize,
                       G_SMEM);
  cudaFuncSetAttribute(flash_tc_kernel,
                       cudaFuncAttributeMaxDynamicSharedMemorySize, F_SMEM_B);

  rope_table_kernel<<<(Sc * 32 + 255) / 256, 256>>>();

  int n4x = Mc * DIMc / 4;
  split_kernel<<<(n4x + 255) / 256, 256>>>(x, xhi, xlo, n4x);
  int n4w = DIMc * DIMc / 4;
  split_w_kernel<<<dim3((n4w + 255) / 256, 4), 256>>>(Wq, Wk, Wv, Wo);

  gemm_tc_qkv<<<dim3(DIMc / 128, Mc / 128, 3), 256, G_SMEM>>>(bq, bk, bv, qp,
                                                              kp, vp);

  int total = Mc * Hc * 32;
  rope_apply_kernel<<<(total + 255) / 256, 256>>>(qp, kp);

  flash_tc_kernel<<<dim3(Sc / 128, Bc * Hc), 256, F_SMEM_B>>>(qp, kp, vp, op);

  split_kernel<<<(n4x + 255) / 256, 256>>>(op, ohi, olo, n4x);
  gemm_tc_out<<<dim3(DIMc / 128, Mc / 128), 256, G_SMEM>>>(bo, out);
}

// round 11
// speedup vs baseline: 2.9369x; 1.1675x over previous
#include <cuda_runtime.h>
#include <cuda_bf16.h>
#include <math.h>
#include <stdint.h>

#define Bc 4
#define Sc 1024
#define DIMc 1024
#define Hc 16
#define DHc 64
#define Mc (Bc * Sc)

// ---------------- scratch (__device__ globals; no allocation allowed) -------
__device__ float g_q[Mc * DIMc];
__device__ float g_k[Mc * DIMc];
__device__ float g_cs[Sc * 32];
__device__ float g_sn[Sc * 32];
__device__ __nv_bfloat16 g_xhi[Mc * DIMc];
__device__ __nv_bfloat16 g_xlo[Mc * DIMc];
__device__ __nv_bfloat16 g_whi[4 * DIMc * DIMc];
__device__ __nv_bfloat16 g_wlo[4 * DIMc * DIMc];
__device__ __nv_bfloat16 g_qhi[Mc * DIMc];
__device__ __nv_bfloat16 g_qlo[Mc * DIMc];
__device__ __nv_bfloat16 g_khi[Mc * DIMc];
__device__ __nv_bfloat16 g_klo[Mc * DIMc];
__device__ __nv_bfloat16 g_vhi[Mc * DIMc];
__device__ __nv_bfloat16 g_vlo[Mc * DIMc];
__device__ __nv_bfloat16 g_ohi[Mc * DIMc];
__device__ __nv_bfloat16 g_olo[Mc * DIMc];

// ---------------- PTX helpers (non-'a' features only) -----------------------
__device__ __forceinline__ uint32_t smem_u32(const void* p) {
  uint32_t a;
  asm("{ .reg .u64 t; cvta.to.shared.u64 t, %1; cvt.u32.u64 %0, t; }"
      : "=r"(a) : "l"(p));
  return a;
}

__device__ __forceinline__ void cpa16(uint32_t dst, const void* src) {
  asm volatile("cp.async.ca.shared.global [%0], [%1], 16;" ::"r"(dst),
               "l"(src));
}
#define CP_COMMIT asm volatile("cp.async.commit_group;" ::: "memory")
#define CP_WAIT1 asm volatile("cp.async.wait_group 1;" ::: "memory")
#define CP_WAIT0 asm volatile("cp.async.wait_group 0;" ::: "memory")

__device__ __forceinline__ void ldm_x4(uint32_t addr, uint32_t* r) {
  asm volatile(
      "ldmatrix.sync.aligned.m8n8.x4.shared.b16 {%0,%1,%2,%3}, [%4];"
      : "=r"(r[0]), "=r"(r[1]), "=r"(r[2]), "=r"(r[3])
      : "r"(addr));
}

__device__ __forceinline__ void ldm_x4_trans(uint32_t addr, uint32_t* r) {
  asm volatile(
      "ldmatrix.sync.aligned.m8n8.x4.trans.shared.b16 {%0,%1,%2,%3}, [%4];"
      : "=r"(r[0]), "=r"(r[1]), "=r"(r[2]), "=r"(r[3])
      : "r"(addr));
}

__device__ __forceinline__ void mma16816(float* c, const uint32_t* a,
                                         const uint32_t* b) {
  asm volatile(
      "mma.sync.aligned.m16n8k16.row.col.f32.bf16.bf16.f32 "
      "{%0,%1,%2,%3}, {%4,%5,%6,%7}, {%8,%9}, {%0,%1,%2,%3};"
      : "+f"(c[0]), "+f"(c[1]), "+f"(c[2]), "+f"(c[3])
      : "r"(a[0]), "r"(a[1]), "r"(a[2]), "r"(a[3]), "r"(b[0]), "r"(b[1]));
}

__device__ __forceinline__ uint32_t packbf(float a, float b) {
  __nv_bfloat162 t(__float2bfloat16(a), __float2bfloat16(b));
  return *(uint32_t*)&t;
}

// ---------------- split kernels (fp32 -> bf16 hi/lo) ------------------------
__global__ void __launch_bounds__(256) split_kernel(
    const float* __restrict__ src, __nv_bfloat16* __restrict__ hi,
    __nv_bfloat16* __restrict__ lo, int n4) {
  int i = blockIdx.x * blockDim.x + threadIdx.x;
  if (i >= n4) return;
  float4 v = ((const float4*)src)[i];
  __nv_bfloat16 h0 = __float2bfloat16(v.x);
  __nv_bfloat16 h1 = __float2bfloat16(v.y);
  __nv_bfloat16 h2 = __float2bfloat16(v.z);
  __nv_bfloat16 h3 = __float2bfloat16(v.w);
  __nv_bfloat162* hp = (__nv_bfloat162*)hi;
  __nv_bfloat162* lp = (__nv_bfloat162*)lo;
  hp[2 * i] = __nv_bfloat162(h0, h1);
  hp[2 * i + 1] = __nv_bfloat162(h2, h3);
  lp[2 * i] = __nv_bfloat162(__float2bfloat16(v.x - __bfloat162float(h0)),
                             __float2bfloat16(v.y - __bfloat162float(h1)));
  lp[2 * i + 1] = __nv_bfloat162(__float2bfloat16(v.z - __bfloat162float(h2)),
                                 __float2bfloat16(v.w - __bfloat162float(h3)));
}

__global__ void __launch_bounds__(256) split_w_kernel(
    const float* __restrict__ Wq, const float* __restrict__ Wk,
    const float* __restrict__ Wv, const float* __restrict__ Wo) {
  int slot = blockIdx.y;
  const float* W = (slot == 0) ? Wq : (slot == 1) ? Wk : (slot == 2) ? Wv : Wo;
  int i = blockIdx.x * blockDim.x + threadIdx.x;
  int n4 = DIMc * DIMc / 4;
  if (i >= n4) return;
  float4 v = ((const float4*)W)[i];
  __nv_bfloat16* hi = g_whi + (size_t)slot * DIMc * DIMc;
  __nv_bfloat16* lo = g_wlo + (size_t)slot * DIMc * DIMc;
  __nv_bfloat16 h0 = __float2bfloat16(v.x);
  __nv_bfloat16 h1 = __float2bfloat16(v.y);
  __nv_bfloat16 h2 = __float2bfloat16(v.z);
  __nv_bfloat16 h3 = __float2bfloat16(v.w);
  __nv_bfloat162* hp = (__nv_bfloat162*)hi;
  __nv_bfloat162* lp = (__nv_bfloat162*)lo;
  hp[2 * i] = __nv_bfloat162(h0, h1);
  hp[2 * i + 1] = __nv_bfloat162(h2, h3);
  lp[2 * i] = __nv_bfloat162(__float2bfloat16(v.x - __bfloat162float(h0)),
                             __float2bfloat16(v.y - __bfloat162float(h1)));
  lp[2 * i + 1] = __nv_bfloat162(__float2bfloat16(v.z - __bfloat162float(h2)),
                                 __float2bfloat16(v.w - __bfloat162float(h3)));
}

// ---------------- HMMA split-bf16 GEMM --------------------------------------
#define ASTRIDE_B 80
#define TILE_B (128 * ASTRIDE_B)
#define STAGE_B (4 * TILE_B)
#define G_SMEM (2 * STAGE_B)

__device__ __forceinline__ void load_stage(
    uint32_t sbase, const __nv_bfloat16* __restrict__ Ahi,
    const __nv_bfloat16* __restrict__ Alo, const __nv_bfloat16* __restrict__ Bhi,
    const __nv_bfloat16* __restrict__ Blo, int row0, int col0, int k0,
    int tid) {
  const __nv_bfloat16* srcs[4];
  srcs[0] = Ahi + (size_t)row0 * DIMc;
  srcs[1] = Alo + (size_t)row0 * DIMc;
  srcs[2] = Bhi + (size_t)col0 * DIMc;
  srcs[3] = Blo + (size_t)col0 * DIMc;
#pragma unroll
  for (int tbl = 0; tbl < 4; tbl++) {
    const __nv_bfloat16* s = srcs[tbl];
    uint32_t dst = sbase + tbl * TILE_B;
#pragma unroll
    for (int it = 0; it < 2; it++) {
      int idx = tid + it * 256;
      int row = idx >> 2, c = idx & 3;
      cpa16(dst + row * ASTRIDE_B + c * 16,
            s + (size_t)row * DIMc + k0 + c * 8);
    }
  }
}

template <int OUTS>
__device__ __forceinline__ void gemm_tc_body(
    const __nv_bfloat16* __restrict__ Ahi, const __nv_bfloat16* __restrict__ Alo,
    const __nv_bfloat16* __restrict__ Whi, const __nv_bfloat16* __restrict__ Wlo,
    const float* __restrict__ bias, float* __restrict__ C,
    __nv_bfloat16* __restrict__ Chi, __nv_bfloat16* __restrict__ Clo) {
  extern __shared__ char smg[];
  uint32_t sb = smem_u32(smg);
  const int tid = threadIdx.x;
  const int lane = tid & 31, wid = tid >> 5;
  const int warpm = wid & 3, warpn = wid >> 2;
  const int row0 = blockIdx.y * 128, col0 = blockIdx.x * 128;

  float acc[2][8][4];
#pragma unroll
  for (int mt = 0; mt < 2; mt++)
#pragma unroll
    for (int j = 0; j < 8; j++)
#pragma unroll
      for (int c = 0; c < 4; c++) acc[mt][j][c] = 0.f;

  const int a_row = lane & 15, a_kof = (lane >> 4) * 8;
  const int b_n = (lane & 7) + ((lane >> 4) * 8);
  const int b_kof = ((lane >> 3) & 1) * 8;

  load_stage(sb, Ahi, Alo, Whi, Wlo, row0, col0, 0, tid);
  CP_COMMIT;

  const int T = DIMc / 32;
  for (int t = 0; t < T; t++) {
    if (t + 1 < T) {
      load_stage(sb + ((t + 1) & 1) * STAGE_B, Ahi, Alo, Whi, Wlo, row0, col0,
                 (t + 1) * 32, tid);
      CP_COMMIT;
      CP_WAIT1;
    } else {
      CP_WAIT0;
    }
    __syncthreads();

    uint32_t st = sb + (t & 1) * STAGE_B;
    uint32_t Ahs = st, Als = st + TILE_B, Bhs = st + 2 * TILE_B,
             Bls = st + 3 * TILE_B;
#pragma unroll
    for (int kk = 0; kk < 32; kk += 16) {
      uint32_t ah[2][4], al[2][4];
#pragma unroll
      for (int mt = 0; mt < 2; mt++) {
        int r = warpm * 32 + mt * 16 + a_row;
        uint32_t off = r * ASTRIDE_B + (kk + a_kof) * 2;
        ldm_x4(Ahs + off, ah[mt]);
        ldm_x4(Als + off, al[mt]);
      }
#pragma unroll
      for (int nt = 0; nt < 4; nt++) {
        uint32_t bh[4], bl[4];
        int n = warpn * 64 + nt * 16 + b_n;
        uint32_t off = n * ASTRIDE_B + (kk + b_kof) * 2;
        ldm_x4(Bhs + off, bh);
        ldm_x4(Bls + off, bl);
#pragma unroll
        for (int mt = 0; mt < 2; mt++) {
#pragma unroll
          for (int s2 = 0; s2 < 2; s2++) {
            float* cc = acc[mt][nt * 2 + s2];
            mma16816(cc, ah[mt], &bh[2 * s2]);
            mma16816(cc, ah[mt], &bl[2 * s2]);
            mma16816(cc, al[mt], &bh[2 * s2]);
          }
        }
      }
    }
    __syncthreads();
  }

#pragma unroll
  for (int mt = 0; mt < 2; mt++) {
#pragma unroll
    for (int j = 0; j < 8; j++) {
      int row = row0 + warpm * 32 + mt * 16 + (lane >> 2);
      int col = col0 + warpn * 64 + j * 8 + (lane & 3) * 2;
      float b0 = bias[col], b1 = bias[col + 1];
      float x0 = acc[mt][j][0] + b0, x1 = acc[mt][j][1] + b1;
      float y0 = acc[mt][j][2] + b0, y1 = acc[mt][j][3] + b1;
      if (OUTS) {
        __nv_bfloat16 h0 = __float2bfloat16(x0), h1 = __float2bfloat16(x1);
        __nv_bfloat16 g0 = __float2bfloat16(y0), g1 = __float2bfloat16(y1);
        *(__nv_bfloat162*)(Chi + (size_t)row * DIMc + col) =
            __nv_bfloat162(h0, h1);
        *(__nv_bfloat162*)(Clo + (size_t)row * DIMc + col) = __nv_bfloat162(
            __float2bfloat16(x0 - __bfloat162float(h0)),
            __float2bfloat16(x1 - __bfloat162float(h1)));
        *(__nv_bfloat162*)(Chi + (size_t)(row + 8) * DIMc + col) =
            __nv_bfloat162(g0, g1);
        *(__nv_bfloat162*)(Clo + (size_t)(row + 8) * DIMc + col) =
            __nv_bfloat162(__float2bfloat16(y0 - __bfloat162float(g0)),
                           __float2bfloat16(y1 - __bfloat162float(g1)));
      } else {
        *(float2*)(C + (size_t)row * DIMc + col) = make_float2(x0, x1);
        *(float2*)(C + (size_t)(row + 8) * DIMc + col) = make_float2(y0, y1);
      }
    }
  }
}

__global__ void __launch_bounds__(256, 2) gemm_tc_qkv(
    const float* __restrict__ bq, const float* __restrict__ bk,
    const float* __restrict__ bv, float* __restrict__ Cq,
    float* __restrict__ Ck) {
  int z = blockIdx.z;
  const __nv_bfloat16* Whi = g_whi + (size_t)z * DIMc * DIMc;
  const __nv_bfloat16* Wlo = g_wlo + (size_t)z * DIMc * DIMc;
  if (z == 2) {
    gemm_tc_body<1>(g_xhi, g_xlo, Whi, Wlo, bv, nullptr, g_vhi, g_vlo);
  } else {
    const float* bias = (z == 0) ? bq : bk;
    float* C = (z == 0) ? Cq : Ck;
    gemm_tc_body<0>(g_xhi, g_xlo, Whi, Wlo, bias, C, nullptr, nullptr);
  }
}

__global__ void __launch_bounds__(256, 2) gemm_tc_out(
    const float* __restrict__ bo, float* __restrict__ C) {
  const __nv_bfloat16* Whi = g_whi + (size_t)3 * DIMc * DIMc;
  const __nv_bfloat16* Wlo = g_wlo + (size_t)3 * DIMc * DIMc;
  gemm_tc_body<0>(g_ohi, g_olo, Whi, Wlo, bo, C, nullptr, nullptr);
}

// ---------------- RoPE: fp32 in, split bf16 out -----------------------------
__global__ void rope_table_kernel() {
  int idx = blockIdx.x * blockDim.x + threadIdx.x;
  if (idx >= Sc * 32) return;
  int j = idx & 31;
  int s = idx >> 5;
  double freq = exp(-(double)j * (log(10000.0) / 32.0));
  double ang = (double)s * freq;
  g_cs[idx] = (float)cos(ang);
  g_sn[idx] = (float)sin(ang);
}

__device__ __forceinline__ void split_store(__nv_bfloat16* hi,
                                            __nv_bfloat16* lo, size_t off,
                                            float v) {
  __nv_bfloat16 h = __float2bfloat16(v);
  hi[off] = h;
  lo[off] = __float2bfloat16(v - __bfloat162float(h));
}

__global__ void __launch_bounds__(256) rope_apply_kernel(
    const float* __restrict__ q, const float* __restrict__ k) {
  int idx = blockIdx.x * blockDim.x + threadIdx.x;
  if (idx >= Mc * Hc * 32) return;
  int j = idx & 31;
  int h = (idx >> 5) & (Hc - 1);
  int m = idx >> 9;
  int s = m & (Sc - 1);
  float cs = g_cs[s * 32 + j];
  float sn = g_sn[s * 32 + j];
  size_t base = (size_t)m * DIMc + h * DHc;
  float q1 = q[base + j], q2 = q[base + j + 32];
  float qr1 = fmaf(q1, cs, -q2 * sn);
  float qr2 = fmaf(q2, cs, q1 * sn);
  split_store(g_qhi, g_qlo, base + j, qr1);
  split_store(g_qhi, g_qlo, base + j + 32, qr2);
  float k1 = k[base + j], k2 = k[base + j + 32];
  float kr1 = fmaf(k1, cs, -k2 * sn);
  float kr2 = fmaf(k2, cs, k1 * sn);
  split_store(g_khi, g_klo, base + j, kr1);
  split_store(g_khi, g_klo, base + j + 32, kr2);
}

// ---------------- Flash attention, HMMA, pre-split inputs -------------------
// Block: 128 q-rows x one (b,h). 8 warps. KV tile 64. cp.async loads.
// V kept row-major [j][d]; B fragments via ldmatrix.trans.
#define FSTR 72
#define FB (FSTR * 2)
#define F_QH 0
#define F_QL 9216
#define F_KH 18432
#define F_KL 23040
#define F_VH 27648
#define F_VL 32256
#define F_SMEM_B (36864 * 2)

__global__ void __launch_bounds__(256, 2) flash_tc_kernel(
    float* __restrict__ o_unused) {
  extern __shared__ __nv_bfloat16 sf[];
  uint32_t sbase = smem_u32(sf);
  const uint32_t QhA = sbase + F_QH * 2, QlA = sbase + F_QL * 2;
  const uint32_t KhA = sbase + F_KH * 2, KlA = sbase + F_KL * 2;
  const uint32_t VhA = sbase + F_VH * 2, VlA = sbase + F_VL * 2;

  const int tid = threadIdx.x, lane = tid & 31, w = tid >> 5;
  const int b = blockIdx.y >> 4, h = blockIdx.y & 15;
  const int q0 = blockIdx.x * 128;
  const size_t hof = (size_t)b * Sc * DIMc + h * DHc;

  // ---- Q tiles via cp.async (hi + lo): 128 rows x 8 chunks each
#pragma unroll
  for (int it = 0; it < 4; it++) {
    int idx = tid + it * 256;
    int row = idx >> 3, c = idx & 7;
    cpa16(QhA + row * FB + c * 16, g_qhi + hof + (size_t)(q0 + row) * DIMc + c * 8);
    cpa16(QlA + row * FB + c * 16, g_qlo + hof + (size_t)(q0 + row) * DIMc + c * 8);
  }
  CP_COMMIT;
  CP_WAIT0;
  __syncthreads();

  const int a_row = lane & 15, a_kof = (lane >> 4) * 8;
  const int b_n = (lane & 7) + ((lane >> 4) * 8);
  const int b_kof = ((lane >> 3) & 1) * 8;
  uint32_t qh[4][4], ql[4][4];
#pragma unroll
  for (int kc = 0; kc < 4; kc++) {
    uint32_t off = (uint32_t)(w * 16 + a_row) * FB + (kc * 16 + a_kof) * 2;
    ldm_x4(QhA + off, qh[kc]);
    ldm_x4(QlA + off, ql[kc]);
  }

  float m0 = -INFINITY, m1 = -INFINITY, l0 = 0.f, l1 = 0.f;
  float acc[8][4];
#pragma unroll
  for (int dt = 0; dt < 8; dt++)
#pragma unroll
    for (int c = 0; c < 4; c++) acc[dt][c] = 0.f;

  const float scale = 0.125f;

  for (int t = 0; t < 16; t++) {
    size_t kvof = hof + (size_t)t * 64 * DIMc;
    __syncthreads();  // previous tile readers done
    // K/V hi+lo tiles: 4 arrays x 64 rows x 8 chunks = 2048 chunks
#pragma unroll
    for (int it = 0; it < 8; it++) {
      int idx = tid + it * 256;
      int arr = idx >> 9, rem = idx & 511;
      int row = rem >> 3, c = rem & 7;
      const __nv_bfloat16* src =
          (arr == 0) ? g_khi : (arr == 1) ? g_klo : (arr == 2) ? g_vhi : g_vlo;
      uint32_t dstA = (arr == 0) ? KhA : (arr == 1) ? KlA : (arr == 2) ? VhA : VlA;
      cpa16(dstA + row * FB + c * 16, src + kvof + (size_t)row * DIMc + c * 8);
    }
    CP_COMMIT;
    CP_WAIT0;
    __syncthreads();

    // ---- S = Q K^T (warp: 16 x 64)
    float s[8][4];
#pragma unroll
    for (int nt = 0; nt < 8; nt++)
#pragma unroll
      for (int c = 0; c < 4; c++) s[nt][c] = 0.f;
#pragma unroll
    for (int kc = 0; kc < 4; kc++) {
#pragma unroll
      for (int ng = 0; ng < 4; ng++) {
        uint32_t bh4[4], bl4[4];
        uint32_t off = (uint32_t)(ng * 16 + b_n) * FB + (kc * 16 + b_kof) * 2;
        ldm_x4(KhA + off, bh4);
        ldm_x4(KlA + off, bl4);
#pragma unroll
        for (int s2 = 0; s2 < 2; s2++) {
          float* cc = s[ng * 2 + s2];
          mma16816(cc, qh[kc], &bh4[2 * s2]);
          mma16816(cc, qh[kc], &bl4[2 * s2]);
          mma16816(cc, ql[kc], &bh4[2 * s2]);
        }
      }
    }

    // ---- online softmax
    float mx0 = -INFINITY, mx1 = -INFINITY;
#pragma unroll
    for (int nt = 0; nt < 8; nt++) {
      s[nt][0] *= scale; s[nt][1] *= scale;
      s[nt][2] *= scale; s[nt][3] *= scale;
      mx0 = fmaxf(mx0, fmaxf(s[nt][0], s[nt][1]));
      mx1 = fmaxf(mx1, fmaxf(s[nt][2], s[nt][3]));
    }
    mx0 = fmaxf(mx0, __shfl_xor_sync(0xffffffffu, mx0, 1));
    mx0 = fmaxf(mx0, __shfl_xor_sync(0xffffffffu, mx0, 2));
    mx1 = fmaxf(mx1, __shfl_xor_sync(0xffffffffu, mx1, 1));
    mx1 = fmaxf(mx1, __shfl_xor_sync(0xffffffffu, mx1, 2));
    float mn0 = fmaxf(m0, mx0), mn1 = fmaxf(m1, mx1);
    float corr0 = __expf(m0 - mn0), corr1 = __expf(m1 - mn1);
    m0 = mn0; m1 = mn1;
    float rs0 = 0.f, rs1 = 0.f;
#pragma unroll
    for (int nt = 0; nt < 8; nt++) {
      s[nt][0] = __expf(s[nt][0] - mn0);
      s[nt][1] = __expf(s[nt][1] - mn0);
      s[nt][2] = __expf(s[nt][2] - mn1);
      s[nt][3] = __expf(s[nt][3] - mn1);
      rs0 += s[nt][0] + s[nt][1];
      rs1 += s[nt][2] + s[nt][3];
    }
    rs0 += __shfl_xor_sync(0xffffffffu, rs0, 1);
    rs0 += __shfl_xor_sync(0xffffffffu, rs0, 2);
    rs1 += __shfl_xor_sync(0xffffffffu, rs1, 1);
    rs1 += __shfl_xor_sync(0xffffffffu, rs1, 2);
    l0 = l0 * corr0 + rs0;
    l1 = l1 * corr1 + rs1;

    // P hi/lo fragments
    uint32_t ph[4][4], pl[4][4];
#pragma unroll
    for (int kc = 0; kc < 4; kc++) {
      float* sa = s[2 * kc];
      float* sbn = s[2 * kc + 1];
      float r0a = __bfloat162float(__float2bfloat16(sa[0]));
      float r0b = __bfloat162float(__float2bfloat16(sa[1]));
      float r1a = __bfloat162float(__float2bfloat16(sa[2]));
      float r1b = __bfloat162float(__float2bfloat16(sa[3]));
      float n0a = __bfloat162float(__float2bfloat16(sbn[0]));
      float n0b = __bfloat162float(__float2bfloat16(sbn[1]));
      float n1a = __bfloat162float(__float2bfloat16(sbn[2]));
      float n1b = __bfloat162float(__float2bfloat16(sbn[3]));
      ph[kc][0] = packbf(sa[0], sa[1]);
      ph[kc][1] = packbf(sa[2], sa[3]);
      ph[kc][2] = packbf(sbn[0], sbn[1]);
      ph[kc][3] = packbf(sbn[2], sbn[3]);
      pl[kc][0] = packbf(sa[0] - r0a, sa[1] - r0b);
      pl[kc][1] = packbf(sa[2] - r1a, sa[3] - r1b);
      pl[kc][2] = packbf(sbn[0] - n0a, sbn[1] - n0b);
      pl[kc][3] = packbf(sbn[2] - n1a, sbn[3] - n1b);
    }

#pragma unroll
    for (int dt = 0; dt < 8; dt++) {
      acc[dt][0] *= corr0; acc[dt][1] *= corr0;
      acc[dt][2] *= corr1; acc[dt][3] *= corr1;
    }

    // ---- O += P V : V row-major [j][d], fragments via ldmatrix.trans
#pragma unroll
    for (int kc = 0; kc < 4; kc++) {
#pragma unroll
      for (int ng = 0; ng < 4; ng++) {
        uint32_t vh4[4], vl4[4];
        // lanes: m0=j0-7/d0-7, m1=j8-15/d0-7, m2=j0-7/d8-15, m3=j8-15/d8-15
        uint32_t off = (uint32_t)(kc * 16 + (lane & 15)) * FB +
                       (ng * 16 + (lane >> 4) * 8) * 2;
        ldm_x4_trans(VhA + off, vh4);
        ldm_x4_trans(VlA + off, vl4);
#pragma unroll
        for (int s2 = 0; s2 < 2; s2++) {
          float* cc = acc[ng * 2 + s2];
          mma16816(cc, ph[kc], &vh4[2 * s2]);
          mma16816(cc, ph[kc], &vl4[2 * s2]);
          mma16816(cc, pl[kc], &vh4[2 * s2]);
        }
      }
    }
  }

  // ---- Writeback directly as hi/lo bf16 (consumed by gemm_tc_out)
  float inv0 = 1.f / l0, inv1 = 1.f / l1;
  int r0 = q0 + w * 16 + (lane >> 2);
#pragma unroll
  for (int dt = 0; dt < 8; dt++) {
    int col = h * DHc + dt * 8 + (lane & 3) * 2;
    float x0 = acc[dt][0] * inv0, x1 = acc[dt][1] * inv0;
    float y0 = acc[dt][2] * inv1, y1 = acc[dt][3] * inv1;
    size_t off0 = (size_t)(b * Sc + r0) * DIMc + col;
    size_t off1 = (size_t)(b * Sc + r0 + 8) * DIMc + col;
    __nv_bfloat16 h0 = __float2bfloat16(x0), h1 = __float2bfloat16(x1);
    __nv_bfloat16 g0 = __float2bfloat16(y0), g1 = __float2bfloat16(y1);
    *(__nv_bfloat162*)(g_ohi + off0) = __nv_bfloat162(h0, h1);
    *(__nv_bfloat162*)(g_olo + off0) =
        __nv_bfloat162(__float2bfloat16(x0 - __bfloat162float(h0)),
                       __float2bfloat16(x1 - __bfloat162float(h1)));
    *(__nv_bfloat162*)(g_ohi + off1) = __nv_bfloat162(g0, g1);
    *(__nv_bfloat162*)(g_olo + off1) =
        __nv_bfloat162(__float2bfloat16(y0 - __bfloat162float(g0)),
                       __float2bfloat16(y1 - __bfloat162float(g1)));
  }
}

// ----------------------------------------------------------------------------
extern "C" void kernel_launch(void* const* d_in, const int* in_sizes, int n_in,
                              void* d_out, int out_size) {
  const float* x = (const float*)d_in[0];
  const float* Wq = (const float*)d_in[1];
  const float* bq = (const float*)d_in[2];
  const float* Wk = (const float*)d_in[3];
  const float* bk = (const float*)d_in[4];
  const float* Wv = (const float*)d_in[5];
  const float* bv = (const float*)d_in[6];
  const float* Wo = (const float*)d_in[7];
  const float* bo = (const float*)d_in[8];
  float* out = (float*)d_out;

  float *qp, *kp;
  cudaGetSymbolAddress((void**)&qp, g_q);
  cudaGetSymbolAddress((void**)&kp, g_k);
  __nv_bfloat16 *xhi, *xlo;
  cudaGetSymbolAddress((void**)&xhi, g_xhi);
  cudaGetSymbolAddress((void**)&xlo, g_xlo);

  cudaFuncSetAttribute(gemm_tc_qkv, cudaFuncAttributeMaxDynamicSharedMemorySize,
                       G_SMEM);
  cudaFuncSetAttribute(gemm_tc_out, cudaFuncAttributeMaxDynamicSharedMemorySize,
                       G_SMEM);
  cudaFuncSetAttribute(flash_tc_kernel,
                       cudaFuncAttributeMaxDynamicSharedMemorySize, F_SMEM_B);

  rope_table_kernel<<<(Sc * 32 + 255) / 256, 256>>>();

  int n4x = Mc * DIMc / 4;
  split_kernel<<<(n4x + 255) / 256, 256>>>(x, xhi, xlo, n4x);
  int n4w = DIMc * DIMc / 4;
  split_w_kernel<<<dim3((n4w + 255) / 256, 4), 256>>>(Wq, Wk, Wv, Wo);

  gemm_tc_qkv<<<dim3(DIMc / 128, Mc / 128, 3), 256, G_SMEM>>>(bq, bk, bv, qp,
                                                              kp);

  int total = Mc * Hc * 32;
  rope_apply_kernel<<<(total + 255) / 256, 256>>>(qp, kp);

  flash_tc_kernel<<<dim3(Sc / 128, Bc * Hc), 256, F_SMEM_B>>>(nullptr);

  gemm_tc_out<<<dim3(DIMc / 128, Mc / 128), 256, G_SMEM>>>(bo, out);
}